// round 16
// baseline (speedup 1.0000x reference)
#include <cuda_runtime.h>
#include <stdint.h>
#include <math.h>

#define IM_FE_RATIO 16.0f
#define TPB 256
#define CHUNK_FLOATS 8192                 // 32 KB per bulk chunk
#define CHUNKS_PER_CTA 2
#define PBUF_FLOATS 2048                  // 8 KB patch buffer (span <= 5W+6+align)

static __device__ __forceinline__ uint32_t smem_u32(const void* p) {
    uint32_t a;
    asm("{ .reg .u64 t; cvta.to.shared.u64 t, %1; cvt.u32.u64 %0, t; }"
        : "=r"(a) : "l"(p));
    return a;
}

static __device__ __forceinline__ void bulk_copy(float* dst, uint32_t src_smem,
                                                 uint32_t bytes) {
    asm volatile(
        "cp.async.bulk.global.shared::cta.bulk_group [%0], [%1], %2;"
        :: "l"(dst), "r"(src_smem), "r"(bytes) : "memory");
}

// One CTA per 2 chunks (64 KB) of one (b,n) plane. Two IMMUTABLE smem
// buffers built once: bufZ (32 KB zeros) and bufP (8 KB: zeros + the 6x6
// blurred-patch span). Each chunk is streamed to global as 1 copy from bufZ,
// or a 3-piece split (bufZ prefix / bufP span / bufZ suffix) when the patch
// intersects it. Copies issue back-to-back, one commit + read-wait at end.
// Halves the STS zero-fill traffic vs one-buffer-per-chunk (R12: L1tex 64%).
__global__ void __launch_bounds__(TPB) inver_interp_bulk4(
    const float* __restrict__ Xg,
    const float* __restrict__ kp,
    const float* __restrict__ gk,
    float* __restrict__ out,
    int N, int H, int W, int HW)
{
    __shared__ float bufZ[CHUNK_FLOATS];  // 32 KB, zeros
    __shared__ float bufP[PBUF_FLOATS];   // 8 KB, zeros + patch cells

    const int b    = blockIdx.z;
    const int row  = b * N + blockIdx.y;
    const int c0   = blockIdx.x * CHUNKS_PER_CTA;   // first chunk index
    const int t    = threadIdx.x;
    const int lane = t & 31;

    // ---- per-warp ballot prologue (Xg row is one-hot or all-zero) ----
    const unsigned FULL = 0xffffffffu;
    float xg = 0.f, kxv = 0.f, kyv = 0.f;
    if (lane < N) {
        xg = Xg[(size_t)row * N + lane];
        const float2 k2 = ((const float2*)kp)[(size_t)b * N + lane];
        kxv = k2.x; kyv = k2.y;
    }
    const unsigned bal = __ballot_sync(FULL, xg != 0.f);
    const bool valid = (bal != 0u);
    const int  j  = valid ? (__ffs(bal) - 1) : 0;
    const float mx = __shfl_sync(FULL, xg,  j);          // mask (0/1)
    const float kx = __shfl_sync(FULL, kxv, j) * mx;
    const float ky = __shfl_sync(FULL, kyv, j) * mx;

    int x0 = 0, y0 = 0, ox1 = 0, oy1 = 0;
    float upx = 0.f, lwx = 0.f, upy = 0.f, lwy = 0.f;
    int pstart = 0, pend = 0;             // patch float range [pstart, pend)
    bool fallback = false;
    if (valid) {
        const float x = kx * (1.0f / IM_FE_RATIO) - 0.5f;
        const float y = ky * (1.0f / IM_FE_RATIO) - 0.5f;
        const float maxx = (float)(W - 1);
        const float maxy = (float)(H - 1);
        const float lox = fminf(fmaxf(floorf(x), 0.0f), maxx);
        const float hix = fminf(fmaxf(ceilf(x),  0.0f), maxx);
        const float loy = fminf(fmaxf(floorf(y), 0.0f), maxy);
        const float hiy = fminf(fmaxf(ceilf(y),  0.0f), maxy);
        x0 = (int)lox; y0 = (int)loy;
        ox1 = (int)hix - x0; oy1 = (int)hiy - y0;
        upx = x - lox; lwx = 1.0f - upx;
        upy = y - loy; lwy = 1.0f - upy;
        const int pyMin = max(0, y0 - 2), pyMax = min(H - 1, y0 + 3);
        const int pxMin = max(0, x0 - 2), pxMax = min(W - 1, x0 + 3);
        const int idx0 = pyMin * W + pxMin;
        const int idx1 = pyMax * W + pxMax;
        pstart = idx0 & ~3;                       // 16B-aligned down
        pend   = min(HW, (idx1 + 4) & ~3);        // 16B-aligned up
        if (pend - pstart > PBUF_FLOATS) fallback = true;  // shouldn't happen
    }

    // ---- build immutable buffers ----
    #pragma unroll
    for (int i = t * 4; i < CHUNK_FLOATS; i += TPB * 4)
        *(float4*)(bufZ + i) = make_float4(0.f, 0.f, 0.f, 0.f);
    #pragma unroll
    for (int i = t * 4; i < PBUF_FLOATS; i += TPB * 4)
        *(float4*)(bufP + i) = make_float4(0.f, 0.f, 0.f, 0.f);
    __syncthreads();

    // patch cell values (one per thread t<36); also kept for fallback STG
    int   myIdx = -1;
    float myVal = 0.f;
    if (valid && t < 36) {
        const int dy = t / 6, dx = t - dy * 6;
        const int py = y0 - 2 + dy, px = x0 - 2 + dx;
        if (py >= 0 && py < H && px >= 0 && px < W) {
            float val = 0.f;
            #pragma unroll
            for (int cy = 0; cy < 2; cy++) {
                const int   oy = cy ? oy1 : 0;
                const float wy = cy ? upy : lwy;
                const int   ki = dy - oy;
                if (ki < 0 || ki > 4) continue;
                #pragma unroll
                for (int cx = 0; cx < 2; cx++) {
                    const int   ox = cx ? ox1 : 0;
                    const float wx = cx ? upx : lwx;
                    const int   kj = dx - ox;
                    if (kj < 0 || kj > 4) continue;
                    val += (wy * wx) * __ldg(gk + ki * 5 + kj);
                }
            }
            myIdx = py * W + px;
            myVal = val;
            if (!fallback) bufP[myIdx - pstart] = val;
        }
    }
    __syncthreads();

    // ---- stream chunks: back-to-back copies, one commit, one read-wait ----
    const int pLo = fallback ? 0 : pstart;    // effective patch window
    const int pHi = fallback ? 0 : pend;
    float* __restrict__ rowout = out + (size_t)row * HW;

    bool scalarTail = false;
    if (t == 0) {
        const uint32_t sZ = smem_u32(bufZ);
        const uint32_t sP = smem_u32(bufP);
        asm volatile("fence.proxy.async.shared::cta;" ::: "memory");
        #pragma unroll
        for (int k = 0; k < CHUNKS_PER_CTA; k++) {
            const int cb = (c0 + k) * CHUNK_FLOATS;
            if (cb >= HW) break;
            const int ce = min(cb + CHUNK_FLOATS, HW);
            if (((ce - cb) & 3) != 0) { scalarTail = true; continue; }
            const int lo = max(cb, pLo);
            const int hi = min(ce, pHi);
            if (hi <= lo) {
                bulk_copy(rowout + cb, sZ, (uint32_t)(ce - cb) * 4u);
            } else {
                if (lo > cb) bulk_copy(rowout + cb, sZ, (uint32_t)(lo - cb) * 4u);
                bulk_copy(rowout + lo, sP + (uint32_t)(lo - pstart) * 4u,
                          (uint32_t)(hi - lo) * 4u);
                if (ce > hi) bulk_copy(rowout + hi, sZ, (uint32_t)(ce - hi) * 4u);
            }
        }
        asm volatile("cp.async.bulk.commit_group;" ::: "memory");
        if (fallback)
            asm volatile("cp.async.bulk.wait_group 0;" ::: "memory");      // writes done
        else
            asm volatile("cp.async.bulk.wait_group.read 0;" ::: "memory"); // reads done
    }
    __syncthreads();   // smem must outlive async reads for all threads

    // ---- rarely-taken generality fallbacks ----
    if (fallback && myIdx >= 0) {
        const int cbLo = c0 * CHUNK_FLOATS;
        const int cbHi = min((c0 + CHUNKS_PER_CTA) * CHUNK_FLOATS, HW);
        if (myIdx >= cbLo && myIdx < cbHi) rowout[myIdx] = myVal;
    }
    if (__syncthreads_or(scalarTail ? 1 : 0)) {
        // tail chunk not 16B-divisible: write it with plain stores
        #pragma unroll
        for (int k = 0; k < CHUNKS_PER_CTA; k++) {
            const int cb = (c0 + k) * CHUNK_FLOATS;
            if (cb >= HW) break;
            const int ce = min(cb + CHUNK_FLOATS, HW);
            if (((ce - cb) & 3) == 0) continue;
            for (int f = cb + t; f < ce; f += TPB) {
                float val = 0.f;
                if (!fallback && f >= pLo && f < pHi) val = bufP[f - pstart];
                rowout[f] = val;
            }
        }
    }
}

extern "C" void kernel_launch(void* const* d_in, const int* in_sizes, int n_in,
                              void* d_out, int out_size) {
    const float* Xg = (const float*)d_in[0];   // (B, N, N)
    const float* kp = (const float*)d_in[1];   // (B, N, 2)
    const float* gk = (const float*)d_in[2];   // (N, 1, 5, 5)

    const int rows = in_sizes[1] / 2;          // B*N
    const int N    = in_sizes[0] / rows;       // N (square one-hot)
    const int B    = rows / N;
    const int HW   = out_size / rows;          // H*W
    int W = (int)(sqrt((double)HW) + 0.5);
    int H = HW / W;

    const int chunksPerPlane = (HW + CHUNK_FLOATS - 1) / CHUNK_FLOATS;
    const int pairsPerPlane  = (chunksPerPlane + CHUNKS_PER_CTA - 1) / CHUNKS_PER_CTA;
    dim3 grid(pairsPerPlane, N, B);

    inver_interp_bulk4<<<grid, TPB>>>(Xg, kp, gk, (float*)d_out, N, H, W, HW);
}

// round 17
// speedup vs baseline: 1.0392x; 1.0392x over previous
#include <cuda_runtime.h>
#include <stdint.h>
#include <math.h>

#define IM_FE_RATIO 16.0f
#define TPB 128
#define CHUNK_FLOATS 4096                 // 16 KB per CTA / per bulk copy

static __device__ __forceinline__ uint32_t smem_u32(const void* p) {
    uint32_t a;
    asm("{ .reg .u64 t; cvta.to.shared.u64 t, %1; cvt.u32.u64 %0, t; }"
        : "=r"(a) : "l"(p));
    return a;
}

// One CTA per 16KB chunk of one (b,n) plane, 128 threads. Zero the smem
// buffer, write any 6x6 blurred-patch cells that fall inside this chunk,
// stream it out with a single cp.async.bulk. Smaller quantum than R12's
// 32KB (which won at 20.8us): doubles resident CTAs/SM (~14 concurrent
// copy chains vs ~5-7), halves the per-CTA chain tail, imbalance <=2%.
// (R16 showed concurrency, not smem traffic, is the binding constraint.)
__global__ void __launch_bounds__(TPB) inver_interp_bulk5(
    const float* __restrict__ Xg,
    const float* __restrict__ kp,
    const float* __restrict__ gk,
    float* __restrict__ out,
    int N, int H, int W, int HW)
{
    __shared__ float buf[CHUNK_FLOATS];   // 16 KB

    const int b     = blockIdx.z;
    const int row   = b * N + blockIdx.y;
    const int chunk = blockIdx.x;
    const int t     = threadIdx.x;
    const int lane  = t & 31;

    const int cbase = chunk * CHUNK_FLOATS;
    const int cfl   = min(CHUNK_FLOATS, HW - cbase);

    // ---- per-warp ballot prologue (Xg row is one-hot or all-zero) ----
    const unsigned FULL = 0xffffffffu;
    float xg = 0.f, kxv = 0.f, kyv = 0.f;
    if (lane < N) {
        xg = Xg[(size_t)row * N + lane];
        const float2 k2 = ((const float2*)kp)[(size_t)b * N + lane];
        kxv = k2.x; kyv = k2.y;
    }
    const unsigned bal = __ballot_sync(FULL, xg != 0.f);
    const bool valid = (bal != 0u);
    const int  j  = valid ? (__ffs(bal) - 1) : 0;
    const float mx = __shfl_sync(FULL, xg,  j);          // mask (0/1)
    const float kx = __shfl_sync(FULL, kxv, j) * mx;
    const float ky = __shfl_sync(FULL, kyv, j) * mx;

    int x0 = 0, y0 = 0, ox1 = 0, oy1 = 0;
    float upx = 0.f, lwx = 0.f, upy = 0.f, lwy = 0.f;
    if (valid) {
        const float x = kx * (1.0f / IM_FE_RATIO) - 0.5f;
        const float y = ky * (1.0f / IM_FE_RATIO) - 0.5f;
        const float maxx = (float)(W - 1);
        const float maxy = (float)(H - 1);
        const float lox = fminf(fmaxf(floorf(x), 0.0f), maxx);
        const float hix = fminf(fmaxf(ceilf(x),  0.0f), maxx);
        const float loy = fminf(fmaxf(floorf(y), 0.0f), maxy);
        const float hiy = fminf(fmaxf(ceilf(y),  0.0f), maxy);
        x0 = (int)lox; y0 = (int)loy;
        ox1 = (int)hix - x0; oy1 = (int)hiy - y0;
        upx = x - lox; lwx = 1.0f - upx;
        upy = y - loy; lwy = 1.0f - upy;
    }

    // ---- zero the buffer (8 x float4 per thread) ----
    #pragma unroll
    for (int i = t * 4; i < CHUNK_FLOATS; i += TPB * 4)
        *(float4*)(buf + i) = make_float4(0.f, 0.f, 0.f, 0.f);
    __syncthreads();

    // ---- patch cells that land in this chunk (one cell per thread t<36) ----
    if (valid && t < 36) {
        const int dy = t / 6, dx = t - dy * 6;
        const int py = y0 - 2 + dy, px = x0 - 2 + dx;
        if (py >= 0 && py < H && px >= 0 && px < W) {
            const int idx = py * W + px;
            if (idx >= cbase && idx < cbase + cfl) {
                float val = 0.f;
                #pragma unroll
                for (int cy = 0; cy < 2; cy++) {
                    const int   oy = cy ? oy1 : 0;
                    const float wy = cy ? upy : lwy;
                    const int   ki = dy - oy;
                    if (ki < 0 || ki > 4) continue;
                    #pragma unroll
                    for (int cx = 0; cx < 2; cx++) {
                        const int   ox = cx ? ox1 : 0;
                        const float wx = cx ? upx : lwx;
                        const int   kj = dx - ox;
                        if (kj < 0 || kj > 4) continue;
                        val += (wy * wx) * __ldg(gk + ki * 5 + kj);
                    }
                }
                buf[idx - cbase] = val;      // mask==1 when valid
            }
        }
    }
    __syncthreads();

    // ---- single bulk copy to global ----
    float* __restrict__ dst = out + (size_t)row * HW + cbase;
    const int cbytes = cfl * 4;
    if ((cbytes & 15) == 0) {
        if (t == 0) {
            asm volatile("fence.proxy.async.shared::cta;" ::: "memory");
            asm volatile(
                "cp.async.bulk.global.shared::cta.bulk_group [%0], [%1], %2;"
                :: "l"(dst), "r"(smem_u32(buf)), "r"((uint32_t)cbytes)
                : "memory");
            asm volatile("cp.async.bulk.commit_group;" ::: "memory");
            asm volatile("cp.async.bulk.wait_group.read 0;" ::: "memory");
        }
        __syncthreads();   // smem must outlive the async read for all threads
    } else {
        // generality fallback: tail chunk not 16B-multiple -> plain stores
        for (int i = t; i < cfl; i += TPB) dst[i] = buf[i];
    }
}

extern "C" void kernel_launch(void* const* d_in, const int* in_sizes, int n_in,
                              void* d_out, int out_size) {
    const float* Xg = (const float*)d_in[0];   // (B, N, N)
    const float* kp = (const float*)d_in[1];   // (B, N, 2)
    const float* gk = (const float*)d_in[2];   // (N, 1, 5, 5)

    const int rows = in_sizes[1] / 2;          // B*N
    const int N    = in_sizes[0] / rows;       // N (square one-hot)
    const int B    = rows / N;
    const int HW   = out_size / rows;          // H*W
    int W = (int)(sqrt((double)HW) + 0.5);
    int H = HW / W;

    const int chunksPerPlane = (HW + CHUNK_FLOATS - 1) / CHUNK_FLOATS;
    dim3 grid(chunksPerPlane, N, B);

    inver_interp_bulk5<<<grid, TPB>>>(Xg, kp, gk, (float*)d_out, N, H, W, HW);
}